// round 12
// baseline (speedup 1.0000x reference)
#include <cuda_runtime.h>
#include <cuda_fp16.h>
#include <cuda_bf16.h>

#define NN 100000
#define DIMV 64
#define EE 1600000
#define CHUNK 512
#define NCHMAX ((NN + CHUNK - 1) / CHUNK)   // 196
#define FULL 0xffffffffu

// Scratch (__device__ globals per allocation-free rule)
__device__ __align__(256) float  g_norm[NN];
__device__ __align__(256) int    g_cnt[NN];      // in-degree counts
__device__ __align__(256) int    g_off[NN];      // CSR offsets; after k_place: segment END
__device__ __align__(256) int    g_csum[NCHMAX]; // per-chunk count sums
__device__ __align__(256) float2 g_edges[EE];    // dst-sorted {src_bits, w}
__device__ __align__(256) __half g_tmpA[NN * DIMV];  // h_cur * norm (fp16)
__device__ __align__(256) __half g_tmpB[NN * DIMV];

// ---------------------------------------------------------------------------
// K0: zero cnt
// ---------------------------------------------------------------------------
__global__ void k_zero(int N) {
    for (int i = blockIdx.x * blockDim.x + threadIdx.x; i < N;
         i += gridDim.x * blockDim.x) {
        g_cnt[i] = 0;
    }
}

// ---------------------------------------------------------------------------
// K1: dst histogram (4 edges/thread)
// ---------------------------------------------------------------------------
__global__ void k_hist(const int* __restrict__ dst, int E) {
    int t = blockIdx.x * blockDim.x + threadIdx.x;
    int e = t * 4;
    if (e + 3 < E) {
        int4 dv = *(const int4*)&dst[e];
        atomicAdd(&g_cnt[dv.x], 1);
        atomicAdd(&g_cnt[dv.y], 1);
        atomicAdd(&g_cnt[dv.z], 1);
        atomicAdd(&g_cnt[dv.w], 1);
    } else {
        for (; e < E; ++e) atomicAdd(&g_cnt[dst[e]], 1);
    }
}

// ---------------------------------------------------------------------------
// Scan step 1: per-chunk sums of g_cnt (warp shuffles)
// ---------------------------------------------------------------------------
__global__ void k_scan1(int N) {
    __shared__ int ws[16];
    int b = blockIdx.x, t = threadIdx.x;
    int i = b * CHUNK + t;
    int v = (i < N) ? g_cnt[i] : 0;
    #pragma unroll
    for (int s = 16; s; s >>= 1) v += __shfl_down_sync(FULL, v, s);
    if ((t & 31) == 0) ws[t >> 5] = v;
    __syncthreads();
    if (t == 0) {
        int x = 0;
        #pragma unroll
        for (int k = 0; k < 16; k++) x += ws[k];
        g_csum[b] = x;
    }
}

// ---------------------------------------------------------------------------
// Scan step 2 (fused base): block base from g_csum[0..b), then intra-chunk
// exclusive scan of g_cnt -> g_off.
// ---------------------------------------------------------------------------
__global__ void k_scan3(int N) {
    __shared__ int wbase[16];
    __shared__ int wtot[16];
    __shared__ int s_base;
    int b = blockIdx.x, t = threadIdx.x;
    int warp = t >> 5, lane = t & 31;

    int bv = (t < b) ? g_csum[t] : 0;
    #pragma unroll
    for (int s = 16; s; s >>= 1) bv += __shfl_down_sync(FULL, bv, s);
    if (lane == 0) wbase[warp] = bv;
    __syncthreads();
    if (t == 0) {
        int x = 0;
        #pragma unroll
        for (int k = 0; k < 16; k++) x += wbase[k];
        s_base = x;
    }

    int i = b * CHUNK + t;
    int x = (i < N) ? g_cnt[i] : 0;
    int incl = x;
    #pragma unroll
    for (int d = 1; d < 32; d <<= 1) {
        int y = __shfl_up_sync(FULL, incl, d);
        if (lane >= d) incl += y;
    }
    if (lane == 31) wtot[warp] = incl;
    __syncthreads();
    if (t < 16) {
        int wv = wtot[t];
        int winc = wv;
        #pragma unroll
        for (int d = 1; d < 16; d <<= 1) {
            int y = __shfl_up_sync(0xffffu, winc, d);
            if (t >= d) winc += y;
        }
        wtot[t] = winc - wv;
    }
    __syncthreads();
    if (i < N) g_off[i] = s_base + wtot[warp] + (incl - x);
}

// ---------------------------------------------------------------------------
// K_place: counting-sort edges by dst. Bumps g_off[d] directly (no g_fill);
// after this kernel g_off[d] = segment END; start = g_off[d] - g_cnt[d].
// ---------------------------------------------------------------------------
__global__ void k_place(const float* __restrict__ w,
                        const int* __restrict__ src,
                        const int* __restrict__ dst, int E) {
    int e = blockIdx.x * blockDim.x + threadIdx.x;
    if (e >= E) return;
    int d = dst[e];
    int p = atomicAdd(&g_off[d], 1);
    g_edges[p] = make_float2(__int_as_float(src[e]), w[e]);
}

// ---------------------------------------------------------------------------
// K_init: warp per node. deg = sum of w over sorted in-edges (coalesced, no
// atomics); norm = rsqrt(max(deg,1)); out = h/3; tmpA = half(h*norm).
// ---------------------------------------------------------------------------
__global__ void k_init(const float* __restrict__ h, float* __restrict__ out,
                       int N) {
    int gw = (blockIdx.x * blockDim.x + threadIdx.x) >> 5;
    if (gw >= N) return;
    int lane = threadIdx.x & 31;
    int cnt = g_cnt[gw];
    int off = g_off[gw] - cnt;   // g_off is segment end after k_place

    float ws = 0.0f;
    for (int j = lane; j < cnt; j += 32) ws += g_edges[off + j].y;
    #pragma unroll
    for (int s = 16; s; s >>= 1) ws += __shfl_down_sync(FULL, ws, s);
    float deg = __shfl_sync(FULL, ws, 0);
    float nrm = rsqrtf(fmaxf(deg, 1.0f));
    if (lane == 0) g_norm[gw] = nrm;

    int idx = gw * DIMV + lane * 2;
    float2 hv = *(const float2*)&h[idx];
    const float third = 1.0f / 3.0f;
    *(float2*)&out[idx] = make_float2(hv.x * third, hv.y * third);
    *(__half2*)&g_tmpA[idx] = __floats2half2_rn(hv.x * nrm, hv.y * nrm);
}

// ---------------------------------------------------------------------------
// K_gather<LAST>: warp per node. Fixed-trip fully-unrolled 32-edge batch with
// per-iteration predication — keeps load batching (MLP) for ALL degrees,
// including the dominant deg<32 case (avg degree = 16).
// ---------------------------------------------------------------------------
template <bool LAST>
__global__ void k_gather(float* __restrict__ out, int N) {
    const __half* __restrict__ tsrc = LAST ? g_tmpB : g_tmpA;
    int gw = (blockIdx.x * blockDim.x + threadIdx.x) >> 5;
    if (gw >= N) return;
    int lane = threadIdx.x & 31;
    int dg  = g_cnt[gw];
    int off = g_off[gw] - dg;    // g_off is segment end after k_place
    float ax = 0.0f, ay = 0.0f;

    for (int base = 0; base < dg; base += 32) {
        int m = dg - base; if (m > 32) m = 32;
        float ex = 0.0f, ey = 0.0f;
        if (lane < m) {
            float2 ed = g_edges[off + base + lane];
            ex = ed.x; ey = ed.y;
        }
        #pragma unroll
        for (int k = 0; k < 32; k++) {
            int   s  = __float_as_int(__shfl_sync(FULL, ex, k));
            float sw = __shfl_sync(FULL, ey, k);
            if (k < m) {
                __half2 hv = *(const __half2*)&tsrc[s * DIMV + lane * 2];
                float2 v = __half22float2(hv);
                ax = fmaf(v.x, sw, ax);
                ay = fmaf(v.y, sw, ay);
            }
        }
    }

    float nrm = g_norm[gw];
    float hx = ax * nrm, hy = ay * nrm;
    int idx = gw * DIMV + lane * 2;
    const float third = 1.0f / 3.0f;
    float2 o = *(float2*)&out[idx];
    o.x += hx * third; o.y += hy * third;
    *(float2*)&out[idx] = o;
    if (!LAST) {
        *(__half2*)&g_tmpB[idx] = __floats2half2_rn(hx * nrm, hy * nrm);
    }
}

// ---------------------------------------------------------------------------
// Launch
// ---------------------------------------------------------------------------
extern "C" void kernel_launch(void* const* d_in, const int* in_sizes, int n_in,
                              void* d_out, int out_size) {
    const float* h   = (const float*)d_in[0];
    const float* w   = (const float*)d_in[1];
    const int*   src = (const int*)d_in[2];
    const int*   dst = (const int*)d_in[3];
    float* out = (float*)d_out;

    const int N = in_sizes[0] / DIMV;   // 100000
    const int E = in_sizes[1];          // 1600000
    const int nch = (N + CHUNK - 1) / CHUNK;

    const int TB = 256;

    // CSR build
    k_zero<<<128, TB>>>(N);
    int hthreads = (E + 3) / 4;
    k_hist<<<(hthreads + TB - 1) / TB, TB>>>(dst, E);
    k_scan1<<<nch, CHUNK>>>(N);
    k_scan3<<<nch, CHUNK>>>(N);
    k_place<<<(E + TB - 1) / TB, TB>>>(w, src, dst, E);

    // norm (from sorted edges) + layer-0 contribution
    int wblocks = (N + 7) / 8;
    k_init<<<wblocks, TB>>>(h, out, N);

    // Layers (warp per node, 8 warps/block)
    k_gather<false><<<wblocks, TB>>>(out, N);   // reads tmpA, writes tmpB
    k_gather<true><<<wblocks, TB>>>(out, N);    // reads tmpB
}

// round 15
// speedup vs baseline: 1.1726x; 1.1726x over previous
#include <cuda_runtime.h>
#include <cuda_fp16.h>
#include <cuda_bf16.h>

#define NN 100000
#define DIMV 64
#define EE 1600000
#define CHUNK 512
#define NCHMAX ((NN + CHUNK - 1) / CHUNK)   // 196
#define FULL 0xffffffffu

// Scratch (__device__ globals per allocation-free rule)
__device__ __align__(256) float  g_norm[NN];
__device__ __align__(256) int    g_cnt[NN];      // in-degree counts
__device__ __align__(256) int    g_off[NN];      // CSR offsets; after k_place: segment END
__device__ __align__(256) int    g_csum[NCHMAX]; // per-chunk count sums
__device__ __align__(256) float2 g_edges[EE];    // dst-sorted {src_bits, w}
__device__ __align__(256) __half g_tmpA[NN * DIMV];  // h_cur * norm (fp16)
__device__ __align__(256) __half g_tmpB[NN * DIMV];

// ---------------------------------------------------------------------------
// K0: zero cnt
// ---------------------------------------------------------------------------
__global__ void k_zero(int N) {
    for (int i = blockIdx.x * blockDim.x + threadIdx.x; i < N;
         i += gridDim.x * blockDim.x) {
        g_cnt[i] = 0;
    }
}

// ---------------------------------------------------------------------------
// K1: dst histogram (4 edges/thread)
// ---------------------------------------------------------------------------
__global__ void k_hist(const int* __restrict__ dst, int E) {
    int t = blockIdx.x * blockDim.x + threadIdx.x;
    int e = t * 4;
    if (e + 3 < E) {
        int4 dv = *(const int4*)&dst[e];
        atomicAdd(&g_cnt[dv.x], 1);
        atomicAdd(&g_cnt[dv.y], 1);
        atomicAdd(&g_cnt[dv.z], 1);
        atomicAdd(&g_cnt[dv.w], 1);
    } else {
        for (; e < E; ++e) atomicAdd(&g_cnt[dst[e]], 1);
    }
}

// ---------------------------------------------------------------------------
// Scan step 1: per-chunk sums of g_cnt (warp shuffles)
// ---------------------------------------------------------------------------
__global__ void k_scan1(int N) {
    __shared__ int ws[16];
    int b = blockIdx.x, t = threadIdx.x;
    int i = b * CHUNK + t;
    int v = (i < N) ? g_cnt[i] : 0;
    #pragma unroll
    for (int s = 16; s; s >>= 1) v += __shfl_down_sync(FULL, v, s);
    if ((t & 31) == 0) ws[t >> 5] = v;
    __syncthreads();
    if (t == 0) {
        int x = 0;
        #pragma unroll
        for (int k = 0; k < 16; k++) x += ws[k];
        g_csum[b] = x;
    }
}

// ---------------------------------------------------------------------------
// Scan step 2 (fused base): block base from g_csum[0..b), then intra-chunk
// exclusive scan of g_cnt -> g_off.
// ---------------------------------------------------------------------------
__global__ void k_scan3(int N) {
    __shared__ int wbase[16];
    __shared__ int wtot[16];
    __shared__ int s_base;
    int b = blockIdx.x, t = threadIdx.x;
    int warp = t >> 5, lane = t & 31;

    int bv = (t < b) ? g_csum[t] : 0;
    #pragma unroll
    for (int s = 16; s; s >>= 1) bv += __shfl_down_sync(FULL, bv, s);
    if (lane == 0) wbase[warp] = bv;
    __syncthreads();
    if (t == 0) {
        int x = 0;
        #pragma unroll
        for (int k = 0; k < 16; k++) x += wbase[k];
        s_base = x;
    }

    int i = b * CHUNK + t;
    int x = (i < N) ? g_cnt[i] : 0;
    int incl = x;
    #pragma unroll
    for (int d = 1; d < 32; d <<= 1) {
        int y = __shfl_up_sync(FULL, incl, d);
        if (lane >= d) incl += y;
    }
    if (lane == 31) wtot[warp] = incl;
    __syncthreads();
    if (t < 16) {
        int wv = wtot[t];
        int winc = wv;
        #pragma unroll
        for (int d = 1; d < 16; d <<= 1) {
            int y = __shfl_up_sync(0xffffu, winc, d);
            if (t >= d) winc += y;
        }
        wtot[t] = winc - wv;
    }
    __syncthreads();
    if (i < N) g_off[i] = s_base + wtot[warp] + (incl - x);
}

// ---------------------------------------------------------------------------
// K_place: counting-sort edges by dst. Bumps g_off[d] directly;
// after this kernel g_off[d] = segment END; start = g_off[d] - g_cnt[d].
// ---------------------------------------------------------------------------
__global__ void k_place(const float* __restrict__ w,
                        const int* __restrict__ src,
                        const int* __restrict__ dst, int E) {
    int e = blockIdx.x * blockDim.x + threadIdx.x;
    if (e >= E) return;
    int d = dst[e];
    int p = atomicAdd(&g_off[d], 1);
    g_edges[p] = make_float2(__int_as_float(src[e]), w[e]);
}

// ---------------------------------------------------------------------------
// K_init: warp per node. deg = sum of w over sorted in-edges; norm; out=h/3;
// tmpA = half(h*norm).
// ---------------------------------------------------------------------------
__global__ void k_init(const float* __restrict__ h, float* __restrict__ out,
                       int N) {
    int gw = (blockIdx.x * blockDim.x + threadIdx.x) >> 5;
    if (gw >= N) return;
    int lane = threadIdx.x & 31;
    int cnt = g_cnt[gw];
    int off = g_off[gw] - cnt;   // g_off is segment end after k_place

    float ws = 0.0f;
    for (int j = lane; j < cnt; j += 32) ws += g_edges[off + j].y;
    #pragma unroll
    for (int s = 16; s; s >>= 1) ws += __shfl_down_sync(FULL, ws, s);
    float deg = __shfl_sync(FULL, ws, 0);
    float nrm = rsqrtf(fmaxf(deg, 1.0f));
    if (lane == 0) g_norm[gw] = nrm;

    int idx = gw * DIMV + lane * 2;
    float2 hv = *(const float2*)&h[idx];
    const float third = 1.0f / 3.0f;
    *(float2*)&out[idx] = make_float2(hv.x * third, hv.y * third);
    *(__half2*)&g_tmpA[idx] = __floats2half2_rn(hv.x * nrm, hv.y * nrm);
}

// ---------------------------------------------------------------------------
// Fully-unrolled B-edge batch: B independent LDG.32s, front-batchable.
// ---------------------------------------------------------------------------
template <int B>
__device__ __forceinline__ void gather_batch(const __half* __restrict__ tsrc,
                                             int p, int lane,
                                             float& ax, float& ay) {
    float ex = 0.0f, ey = 0.0f;
    if (B == 32 || lane < B) {
        float2 ed = g_edges[p + lane];
        ex = ed.x; ey = ed.y;
    }
    #pragma unroll
    for (int k = 0; k < B; k++) {
        int   s  = __float_as_int(__shfl_sync(FULL, ex, k));
        float sw = __shfl_sync(FULL, ey, k);
        __half2 hv = *(const __half2*)&tsrc[s * DIMV + lane * 2];
        float2 v = __half22float2(hv);
        ax = fmaf(v.x, sw, ax);
        ay = fmaf(v.y, sw, ay);
    }
}

// ---------------------------------------------------------------------------
// K_gather<LAST>: warp per node. Degree-adaptive compile-time batch ladder
// (32*/16/8/4 + serial tail <=3). Every batch is fully unrolled -> MLP=B,
// and issue count tracks actual degree (avg 16 -> one batch<16>).
// ---------------------------------------------------------------------------
template <bool LAST>
__global__ void k_gather(float* __restrict__ out, int N) {
    const __half* __restrict__ tsrc = LAST ? g_tmpB : g_tmpA;
    int gw = (blockIdx.x * blockDim.x + threadIdx.x) >> 5;
    if (gw >= N) return;
    int lane = threadIdx.x & 31;
    int dg  = g_cnt[gw];
    int p   = g_off[gw] - dg;    // segment start (g_off = end after k_place)
    int rem = dg;
    float ax = 0.0f, ay = 0.0f;

    while (rem >= 32) { gather_batch<32>(tsrc, p, lane, ax, ay); p += 32; rem -= 32; }
    if (rem >= 16)    { gather_batch<16>(tsrc, p, lane, ax, ay); p += 16; rem -= 16; }
    if (rem >= 8)     { gather_batch<8> (tsrc, p, lane, ax, ay); p += 8;  rem -= 8;  }
    if (rem >= 4)     { gather_batch<4> (tsrc, p, lane, ax, ay); p += 4;  rem -= 4;  }

    // serial tail (0..3 edges)
    if (rem > 0) {
        float ex = 0.0f, ey = 0.0f;
        if (lane < rem) {
            float2 ed = g_edges[p + lane];
            ex = ed.x; ey = ed.y;
        }
        #pragma unroll
        for (int k = 0; k < 3; k++) {
            if (k < rem) {
                int   s  = __float_as_int(__shfl_sync(FULL, ex, k));
                float sw = __shfl_sync(FULL, ey, k);
                __half2 hv = *(const __half2*)&tsrc[s * DIMV + lane * 2];
                float2 v = __half22float2(hv);
                ax = fmaf(v.x, sw, ax);
                ay = fmaf(v.y, sw, ay);
            }
        }
    }

    float nrm = g_norm[gw];
    float hx = ax * nrm, hy = ay * nrm;
    int idx = gw * DIMV + lane * 2;
    const float third = 1.0f / 3.0f;
    float2 o = *(float2*)&out[idx];
    o.x += hx * third; o.y += hy * third;
    *(float2*)&out[idx] = o;
    if (!LAST) {
        *(__half2*)&g_tmpB[idx] = __floats2half2_rn(hx * nrm, hy * nrm);
    }
}

// ---------------------------------------------------------------------------
// Launch
// ---------------------------------------------------------------------------
extern "C" void kernel_launch(void* const* d_in, const int* in_sizes, int n_in,
                              void* d_out, int out_size) {
    const float* h   = (const float*)d_in[0];
    const float* w   = (const float*)d_in[1];
    const int*   src = (const int*)d_in[2];
    const int*   dst = (const int*)d_in[3];
    float* out = (float*)d_out;

    const int N = in_sizes[0] / DIMV;   // 100000
    const int E = in_sizes[1];          // 1600000
    const int nch = (N + CHUNK - 1) / CHUNK;

    const int TB = 256;

    // CSR build
    k_zero<<<128, TB>>>(N);
    int hthreads = (E + 3) / 4;
    k_hist<<<(hthreads + TB - 1) / TB, TB>>>(dst, E);
    k_scan1<<<nch, CHUNK>>>(N);
    k_scan3<<<nch, CHUNK>>>(N);
    k_place<<<(E + TB - 1) / TB, TB>>>(w, src, dst, E);

    // norm (from sorted edges) + layer-0 contribution
    int wblocks = (N + 7) / 8;
    k_init<<<wblocks, TB>>>(h, out, N);

    // Layers (warp per node, 8 warps/block)
    k_gather<false><<<wblocks, TB>>>(out, N);   // reads tmpA, writes tmpB
    k_gather<true><<<wblocks, TB>>>(out, N);    // reads tmpB
}